// round 14
// baseline (speedup 1.0000x reference)
#include <cuda_runtime.h>
#include <cuda_bf16.h>
#include <math.h>

#define MAX_NODES 1000000

// Pre-scaled nodal displacement: {ux*u_c, uy*u_c, th*theta_c, 0}
__device__ float4 g_pred4[MAX_NODES];
// Element-force accumulator. INVARIANT: zero at every kernel_launch entry
// (static zero-init for launch #1; node_kernel re-zeros it each launch).
__device__ float4 g_Fint4[MAX_NODES];
__device__ double g_acc[2] = {0.0, 0.0};  // [0]=sum(R_free^2) [1]=sum(F_free^2)
__device__ unsigned g_done = 0u;          // last-block ticket (reset each launch)

// ---------------------------------------------------------------------------
// Kernel 1: prep — pred-only now. 512 nodes/block, 2 nodes/thread,
// smem-staged coalesced reads, coalesced float4 writes. PDL trigger at end.
// ---------------------------------------------------------------------------
#define PTB 256          // threads
#define NPB 512          // nodes per block

__global__ void __launch_bounds__(PTB)
prep_kernel(const float4* __restrict__ pred4,   // 3N/4 float4
            const float* __restrict__ u_c,
            const float* __restrict__ theta_c,
            int N)
{
    __shared__ float spred[3 * NPB];   // 6 KB

    int tid  = threadIdx.x;
    int b    = blockIdx.x;
    int base = b * NPB;

    int npred4 = (3 * N) >> 2;

    {
        int g0 = b * 384 + tid;                     // round 0: 256 float4
        float4 p0 = (g0 < npred4) ? __ldcs(&pred4[g0]) : make_float4(0,0,0,0);
        int g1 = b * 384 + 256 + tid;               // round 1: 128 float4
        float4 p1 = make_float4(0,0,0,0);
        if (tid < 128 && g1 < npred4) p1 = __ldcs(&pred4[g1]);
        ((float4*)spred)[tid] = p0;
        if (tid < 128) ((float4*)spred)[256 + tid] = p1;
    }
    __syncthreads();

    float su = __ldg(u_c);
    float st = __ldg(theta_c);

    #pragma unroll
    for (int k = 0; k < 2; ++k) {
        int node = base + k * PTB + tid;
        if (node >= N) continue;
        int si = k * PTB + tid;
        float px = spred[3 * si + 0];
        float py = spred[3 * si + 1];
        float pt = spred[3 * si + 2];
        g_pred4[node] = make_float4(px * su, py * su, pt * st, 0.f);
    }

    cudaTriggerProgrammaticLaunchCompletion();
}

// ---------------------------------------------------------------------------
// Kernel 2: element pass — unchanged from the passing R13 version.
// ---------------------------------------------------------------------------
#define ETB 256
#define EPB (4 * ETB)    // 1024 elements per block

__device__ __forceinline__ void elem_force(
    float c, float s, float4 dA, float4 dB, float L, float EA, float EI,
    float& fAx, float& fAy, float& f2o, float& f5o)
{
    float thA = -dA.z;
    float thB = -dB.z;

    float u_A =  c * dA.x + s * dA.y;
    float w_A = -s * dA.x + c * dA.y;
    float u_B =  c * dB.x + s * dB.y;
    float w_B = -s * dB.x + c * dB.y;

    float inv_l = 1.0f / L;
    float ea_l  = EA * inv_l;
    float ei_l  = EI * inv_l;
    float ei_l2 = ei_l * inv_l;
    float ei_l3 = ei_l2 * inv_l;

    float dw = w_A - w_B;
    float f0 = ea_l * (u_A - u_B);
    float f1 = 12.0f * ei_l3 * dw + 6.0f * ei_l2 * (thA + thB);
    f2o = 6.0f * ei_l2 * dw + 4.0f * ei_l * thA + 2.0f * ei_l * thB;
    f5o = 6.0f * ei_l2 * dw + 2.0f * ei_l * thA + 4.0f * ei_l * thB;

    fAx = c * f0 - s * f1;
    fAy = s * f0 + c * f1;
}

__device__ __forceinline__ void red_v4(float4* p, float a, float b, float cc)
{
    asm volatile("red.global.add.v4.f32 [%0], {%1, %2, %3, %4};"
                 :: "l"(p), "f"(a), "f"(b), "f"(cc), "f"(0.f)
                 : "memory");
}

__global__ void __launch_bounds__(ETB)
elem_kernel(const float4* __restrict__ len4,
            const float4* __restrict__ pE4,
            const float4* __restrict__ pA4,
            const float4* __restrict__ pI4,
            const float4* __restrict__ dir4,    // 3E/4 float4
            const int4*  __restrict__ conn4,    // E/2 int4
            int E)
{
    __shared__ float sdir[3 * EPB];             // 12 KB
    __shared__ int   sconn[2 * EPB];            // 8 KB

    int tid = threadIdx.x;
    int b   = blockIdx.x;

    // ---- phase 1: prep-independent streaming (overlaps prep via PDL) ----
    int ndir4  = (3 * E) >> 2;
    int nconn4 = E >> 1;
    #pragma unroll
    for (int k = 0; k < 3; ++k) {
        int g = b * 768 + k * ETB + tid;
        ((float4*)sdir)[k * ETB + tid] =
            (g < ndir4) ? __ldcs(&dir4[g]) : make_float4(0,0,0,0);
    }
    #pragma unroll
    for (int k = 0; k < 2; ++k) {
        int g = b * 512 + k * ETB + tid;
        ((int4*)sconn)[k * ETB + tid] =
            (g < nconn4) ? __ldcs(&conn4[g]) : make_int4(0,0,0,0);
    }

    int qt = b * ETB + tid;          // quad index: elements 4qt..4qt+3
    int nquad = E >> 2;

    float4 Lq = make_float4(1,1,1,1), Eq = make_float4(0,0,0,0);
    float4 Aq = Eq, Iq = Eq;
    if (qt < nquad) {
        Lq = __ldcs(&len4[qt]);
        Eq = __ldcs(&pE4[qt]);
        Aq = __ldcs(&pA4[qt]);
        Iq = __ldcs(&pI4[qt]);
    }
    __syncthreads();

    if (qt >= nquad) {
        cudaGridDependencySynchronize();
        cudaTriggerProgrammaticLaunchCompletion();
        return;
    }

    int4 ca = ((const int4*)sconn)[2 * tid + 0];   // {nA0,nB0,nA1,nB1}
    int4 cb = ((const int4*)sconn)[2 * tid + 1];   // {nA2,nB2,nA3,nB3}
    float4 q0 = ((const float4*)sdir)[3 * tid + 0];
    float4 q1 = ((const float4*)sdir)[3 * tid + 1];
    float4 q2 = ((const float4*)sdir)[3 * tid + 2];

    // ---- phase 2: wait for prep's completed writes, then gather/scatter ----
    cudaGridDependencySynchronize();

    float4 dA0 = __ldg(&g_pred4[ca.x]);
    float4 dB0 = __ldg(&g_pred4[ca.y]);
    float4 dA1 = __ldg(&g_pred4[ca.z]);
    float4 dB1 = __ldg(&g_pred4[ca.w]);
    float4 dA2 = __ldg(&g_pred4[cb.x]);
    float4 dB2 = __ldg(&g_pred4[cb.y]);
    float4 dA3 = __ldg(&g_pred4[cb.z]);
    float4 dB3 = __ldg(&g_pred4[cb.w]);

    float c0 = q0.x, s0 = q0.z;
    float c1 = q0.w, s1 = q1.y;
    float c2 = q1.z, s2 = q2.x;
    float c3 = q2.y, s3 = q2.w;

    float fAx, fAy, f2, f5;

    elem_force(c0, s0, dA0, dB0, Lq.x, Eq.x * Aq.x, Eq.x * Iq.x, fAx, fAy, f2, f5);
    red_v4(&g_Fint4[ca.x],  fAx,  fAy, -f2);
    red_v4(&g_Fint4[ca.y], -fAx, -fAy, -f5);

    elem_force(c1, s1, dA1, dB1, Lq.y, Eq.y * Aq.y, Eq.y * Iq.y, fAx, fAy, f2, f5);
    red_v4(&g_Fint4[ca.z],  fAx,  fAy, -f2);
    red_v4(&g_Fint4[ca.w], -fAx, -fAy, -f5);

    elem_force(c2, s2, dA2, dB2, Lq.z, Eq.z * Aq.z, Eq.z * Iq.z, fAx, fAy, f2, f5);
    red_v4(&g_Fint4[cb.x],  fAx,  fAy, -f2);
    red_v4(&g_Fint4[cb.y], -fAx, -fAy, -f5);

    elem_force(c3, s3, dA3, dB3, Lq.w, Eq.w * Aq.w, Eq.w * Iq.w, fAx, fAy, f2, f5);
    red_v4(&g_Fint4[cb.z],  fAx,  fAy, -f2);
    red_v4(&g_Fint4[cb.w], -fAx, -fAy, -f5);

    cudaTriggerProgrammaticLaunchCompletion();
}

// ---------------------------------------------------------------------------
// Kernel 3: node pass — 1024 nodes/block, 4 nodes/thread. PDL phase 1
// preloads F_ext (smem-staged) + bc (direct coalesced) BEFORE the grid sync;
// then reads g_Fint4, computes both sums, re-zeros g_Fint4 for next launch,
// last block writes out and resets accumulators.
// ---------------------------------------------------------------------------
#define NTB 256
#define NNB 1024         // nodes per block

__global__ void __launch_bounds__(NTB)
node_kernel(const float4* __restrict__ fext4,   // 3N/4 float4
            const float* __restrict__ bc_disp,  // N
            const float* __restrict__ bc_rot,   // N
            float* __restrict__ out, int N)
{
    __shared__ float sfext[3 * NNB];   // 12 KB

    int tid  = threadIdx.x;
    int b    = blockIdx.x;
    int base = b * NNB;

    int npred4 = (3 * N) >> 2;

    // ---- phase 1: elem-independent preloads (overlap elem tail) ----
    float bd[4], br[4];
    #pragma unroll
    for (int k = 0; k < 4; ++k) {
        int n = base + k * NTB + tid;
        bool v = (n < N);
        bd[k] = v ? __ldcs(&bc_disp[n]) : 1.f;   // masked out if OOB
        br[k] = v ? __ldcs(&bc_rot[n])  : 1.f;
    }
    #pragma unroll
    for (int k = 0; k < 3; ++k) {
        int g = b * 768 + k * NTB + tid;
        ((float4*)sfext)[k * NTB + tid] =
            (g < npred4) ? __ldcs(&fext4[g]) : make_float4(0,0,0,0);
    }
    __syncthreads();

    // ---- phase 2: wait for elem, read + zero Fint, compute sums ----
    cudaGridDependencySynchronize();

    float4 v[4];
    #pragma unroll
    for (int k = 0; k < 4; ++k) {
        int idx = base + k * NTB + tid;
        v[k] = (idx < N) ? g_Fint4[idx] : make_float4(0.f, 0.f, 0.f, 0.f);
    }
    // re-zero for next launch (maintains the zero-at-entry invariant)
    const float4 z4 = make_float4(0.f, 0.f, 0.f, 0.f);
    #pragma unroll
    for (int k = 0; k < 4; ++k) {
        int idx = base + k * NTB + tid;
        if (idx < N) g_Fint4[idx] = z4;
    }

    float r2 = 0.f, f2 = 0.f;
    #pragma unroll
    for (int k = 0; k < 4; ++k) {
        int idx = base + k * NTB + tid;
        if (idx >= N) continue;
        int si = k * NTB + tid;
        float fx = sfext[3 * si + 0];
        float fy = sfext[3 * si + 1];
        float fz = sfext[3 * si + 2];
        float md = 1.f - bd[k];
        float mr = 1.f - br[k];

        float R0 = (v[k].x - fx) * md;
        float R1 = (v[k].y - fy) * md;
        float R2 = (v[k].z - fz) * mr;
        float G0 = fx * md;
        float G1 = fy * md;
        float G2 = fz * mr;
        r2 += R0 * R0 + R1 * R1 + R2 * R2;
        f2 += G0 * G0 + G1 * G1 + G2 * G2;
    }

    for (int off = 16; off > 0; off >>= 1) {
        r2 += __shfl_down_sync(0xffffffffu, r2, off);
        f2 += __shfl_down_sync(0xffffffffu, f2, off);
    }

    __shared__ float sr[8], sf2[8];
    int lane = tid & 31;
    int wid  = tid >> 5;
    if (lane == 0) { sr[wid] = r2; sf2[wid] = f2; }
    __syncthreads();

    if (wid == 0) {
        float rr = (lane < 8) ? sr[lane]  : 0.f;
        float ff = (lane < 8) ? sf2[lane] : 0.f;
        for (int off = 4; off > 0; off >>= 1) {
            rr += __shfl_down_sync(0xffffffffu, rr, off);
            ff += __shfl_down_sync(0xffffffffu, ff, off);
        }
        if (lane == 0) {
            atomicAdd(&g_acc[0], (double)rr);
            atomicAdd(&g_acc[1], (double)ff);
            __threadfence();
            unsigned ticket = atomicAdd(&g_done, 1u);
            if (ticket == gridDim.x - 1) {
                double fn = g_acc[1];
                if (fn < 1e-30) fn = 1e-30;
                out[0] = (float)(g_acc[0] / fn);
                g_acc[0] = 0.0;
                g_acc[1] = 0.0;
                g_done = 0u;
            }
        }
    }
}

// ---------------------------------------------------------------------------
// Launch — prep plain; elem and node via PDL
// ---------------------------------------------------------------------------
extern "C" void kernel_launch(void* const* d_in, const int* in_sizes, int n_in,
                              void* d_out, int out_size)
{
    const float* pred_raw = (const float*)d_in[0];   // [N,3]
    const float* u_c      = (const float*)d_in[1];   // [1]
    const float* theta_c  = (const float*)d_in[2];   // [1]
    const float* elem_len = (const float*)d_in[3];   // [E]
    const float* prop_E   = (const float*)d_in[4];   // [E]
    const float* prop_A   = (const float*)d_in[5];   // [E]
    const float* prop_I   = (const float*)d_in[6];   // [E]
    const float* dirs     = (const float*)d_in[7];   // [E,3]
    const float* F_ext    = (const float*)d_in[8];   // [N,3]
    const float* bc_disp  = (const float*)d_in[9];   // [N,1]
    const float* bc_rot   = (const float*)d_in[10];  // [N,1]
    const int*   conn     = (const int*)d_in[11];    // [E,2]

    int N = in_sizes[0] / 3;
    int E = in_sizes[3];

    float* out = (float*)d_out;

    prep_kernel<<<(N + NPB - 1) / NPB, PTB>>>(
        (const float4*)pred_raw, u_c, theta_c, N);

    cudaLaunchAttribute attr[1];
    attr[0].id = cudaLaunchAttributeProgrammaticStreamSerialization;
    attr[0].val.programmaticStreamSerializationAllowed = 1;

    {
        cudaLaunchConfig_t cfg = {};
        cfg.gridDim  = dim3((E + EPB - 1) / EPB);
        cfg.blockDim = dim3(ETB);
        cfg.dynamicSmemBytes = 0;
        cfg.stream = 0;
        cfg.attrs = attr;
        cfg.numAttrs = 1;
        cudaLaunchKernelEx(&cfg, elem_kernel,
                           (const float4*)elem_len, (const float4*)prop_E,
                           (const float4*)prop_A, (const float4*)prop_I,
                           (const float4*)dirs, (const int4*)conn, E);
    }

    {
        cudaLaunchConfig_t cfg = {};
        cfg.gridDim  = dim3((N + NNB - 1) / NNB);
        cfg.blockDim = dim3(NTB);
        cfg.dynamicSmemBytes = 0;
        cfg.stream = 0;
        cfg.attrs = attr;
        cfg.numAttrs = 1;
        cudaLaunchKernelEx(&cfg, node_kernel,
                           (const float4*)F_ext, bc_disp, bc_rot, out, N);
    }
}

// round 15
// speedup vs baseline: 1.0660x; 1.0660x over previous
#include <cuda_runtime.h>
#include <cuda_bf16.h>
#include <math.h>

#define MAX_NODES 1000000

// Pre-scaled nodal displacement: {ux*u_c, uy*u_c, th*theta_c, 0}
__device__ float4 g_pred4[MAX_NODES];
// Accumulator: prep sets {-Fe_x, -Fe_y, -Fe_z, packed_masks}; elements add
// forces (w += 0.0f) so after elem pass it holds {R_x, R_y, R_z, masks}.
__device__ float4 g_Fint4[MAX_NODES];
__device__ double g_acc[2] = {0.0, 0.0};  // [0]=sum(R_free^2) [1]=sum(F_free^2)
__device__ unsigned g_done = 0u;          // last-block ticket (reset each launch)

// ---------------------------------------------------------------------------
// Kernel 1: prep — R13 shape (512 nodes/block, 2 nodes/thread) with PDL
// phase split: ALL input loads before the grid-dependency sync (independent
// of the previous replay's node_kernel), writes after. Trigger at end.
// ---------------------------------------------------------------------------
#define PTB 256          // threads
#define NPB 512          // nodes per block

__global__ void __launch_bounds__(PTB)
prep_kernel(const float4* __restrict__ pred4,   // 3N/4 float4
            const float4* __restrict__ fext4,   // 3N/4 float4
            const float* __restrict__ bc_disp,  // N
            const float* __restrict__ bc_rot,   // N
            const float* __restrict__ u_c,
            const float* __restrict__ theta_c,
            int N)
{
    __shared__ float spred[3 * NPB];   // 6 KB
    __shared__ float sfext[3 * NPB];   // 6 KB

    int tid  = threadIdx.x;
    int b    = blockIdx.x;
    int base = b * NPB;

    int npred4 = (3 * N) >> 2;

    int n0 = base + tid;
    int n1 = base + PTB + tid;
    bool v0 = (n0 < N);
    bool v1 = (n1 < N);

    // ---- phase 1: input-only loads (no conflict with prior node_kernel) ----
    float bd0 = v0 ? __ldcs(&bc_disp[n0]) : 0.f;
    float br0 = v0 ? __ldcs(&bc_rot[n0])  : 0.f;
    float bd1 = v1 ? __ldcs(&bc_disp[n1]) : 0.f;
    float br1 = v1 ? __ldcs(&bc_rot[n1])  : 0.f;

    {
        int g0 = b * 384 + tid;                     // round 0: 256 float4
        float4 p0 = (g0 < npred4) ? __ldcs(&pred4[g0]) : make_float4(0,0,0,0);
        float4 f0 = (g0 < npred4) ? __ldcs(&fext4[g0]) : make_float4(0,0,0,0);
        int g1 = b * 384 + 256 + tid;               // round 1: 128 float4
        float4 p1 = make_float4(0,0,0,0), f1 = p1;
        if (tid < 128) {
            if (g1 < npred4) { p1 = __ldcs(&pred4[g1]); f1 = __ldcs(&fext4[g1]); }
        }
        ((float4*)spred)[tid] = p0;
        ((float4*)sfext)[tid] = f0;
        if (tid < 128) {
            ((float4*)spred)[256 + tid] = p1;
            ((float4*)sfext)[256 + tid] = f1;
        }
    }
    __syncthreads();

    float su = __ldg(u_c);
    float st = __ldg(theta_c);

    // ---- phase 2: wait for predecessor (prev replay's node), then write ----
    cudaGridDependencySynchronize();

    float f2 = 0.f;
    #pragma unroll
    for (int k = 0; k < 2; ++k) {
        int node = (k == 0) ? n0 : n1;
        if (node >= N) continue;
        int si = (k == 0) ? tid : (tid + PTB);

        float px = spred[3 * si + 0];
        float py = spred[3 * si + 1];
        float pt = spred[3 * si + 2];
        float fx = sfext[3 * si + 0];
        float fy = sfext[3 * si + 1];
        float fz = sfext[3 * si + 2];
        float md = 1.f - ((k == 0) ? bd0 : bd1);
        float mr = 1.f - ((k == 0) ? br0 : br1);

        g_pred4[node] = make_float4(px * su, py * su, pt * st, 0.f);
        float w = md + 2.f * mr;                  // {0,1,2,3} exact
        g_Fint4[node] = make_float4(-fx, -fy, -fz, w);

        float G0 = fx * md;
        float G1 = fy * md;
        float G2 = fz * mr;
        f2 += G0 * G0 + G1 * G1 + G2 * G2;
    }

    for (int off = 16; off > 0; off >>= 1)
        f2 += __shfl_down_sync(0xffffffffu, f2, off);
    __shared__ float sf[8];
    int lane = tid & 31;
    int wid  = tid >> 5;
    if (lane == 0) sf[wid] = f2;
    __syncthreads();
    if (wid == 0) {
        float ff = (lane < 8) ? sf[lane] : 0.f;
        for (int off = 4; off > 0; off >>= 1)
            ff += __shfl_down_sync(0xffffffffu, ff, off);
        if (lane == 0) atomicAdd(&g_acc[1], (double)ff);
    }

    cudaTriggerProgrammaticLaunchCompletion();
}

// ---------------------------------------------------------------------------
// Kernel 2: element pass — proven R13 version (ETB=256, 4 elem/thread,
// vector LDS re-reads, v4 RED.128). PDL phases + end trigger.
// ---------------------------------------------------------------------------
#define ETB 256
#define EPB (4 * ETB)    // 1024 elements per block

__device__ __forceinline__ void elem_force(
    float c, float s, float4 dA, float4 dB, float L, float EA, float EI,
    float& fAx, float& fAy, float& f2o, float& f5o)
{
    float thA = -dA.z;
    float thB = -dB.z;

    float u_A =  c * dA.x + s * dA.y;
    float w_A = -s * dA.x + c * dA.y;
    float u_B =  c * dB.x + s * dB.y;
    float w_B = -s * dB.x + c * dB.y;

    float inv_l = 1.0f / L;
    float ea_l  = EA * inv_l;
    float ei_l  = EI * inv_l;
    float ei_l2 = ei_l * inv_l;
    float ei_l3 = ei_l2 * inv_l;

    float dw = w_A - w_B;
    float f0 = ea_l * (u_A - u_B);
    float f1 = 12.0f * ei_l3 * dw + 6.0f * ei_l2 * (thA + thB);
    f2o = 6.0f * ei_l2 * dw + 4.0f * ei_l * thA + 2.0f * ei_l * thB;
    f5o = 6.0f * ei_l2 * dw + 2.0f * ei_l * thA + 4.0f * ei_l * thB;

    fAx = c * f0 - s * f1;
    fAy = s * f0 + c * f1;
}

__device__ __forceinline__ void red_v4(float4* p, float a, float b, float cc)
{
    asm volatile("red.global.add.v4.f32 [%0], {%1, %2, %3, %4};"
                 :: "l"(p), "f"(a), "f"(b), "f"(cc), "f"(0.f)
                 : "memory");
}

__global__ void __launch_bounds__(ETB)
elem_kernel(const float4* __restrict__ len4,
            const float4* __restrict__ pE4,
            const float4* __restrict__ pA4,
            const float4* __restrict__ pI4,
            const float4* __restrict__ dir4,    // 3E/4 float4
            const int4*  __restrict__ conn4,    // E/2 int4
            int E)
{
    __shared__ float sdir[3 * EPB];             // 12 KB
    __shared__ int   sconn[2 * EPB];            // 8 KB

    int tid = threadIdx.x;
    int b   = blockIdx.x;

    // ---- phase 1: prep-independent streaming ----
    int ndir4  = (3 * E) >> 2;
    int nconn4 = E >> 1;
    #pragma unroll
    for (int k = 0; k < 3; ++k) {
        int g = b * 768 + k * ETB + tid;
        ((float4*)sdir)[k * ETB + tid] =
            (g < ndir4) ? __ldcs(&dir4[g]) : make_float4(0,0,0,0);
    }
    #pragma unroll
    for (int k = 0; k < 2; ++k) {
        int g = b * 512 + k * ETB + tid;
        ((int4*)sconn)[k * ETB + tid] =
            (g < nconn4) ? __ldcs(&conn4[g]) : make_int4(0,0,0,0);
    }

    int qt = b * ETB + tid;          // quad index: elements 4qt..4qt+3
    int nquad = E >> 2;

    float4 Lq = make_float4(1,1,1,1), Eq = make_float4(0,0,0,0);
    float4 Aq = Eq, Iq = Eq;
    if (qt < nquad) {
        Lq = __ldcs(&len4[qt]);
        Eq = __ldcs(&pE4[qt]);
        Aq = __ldcs(&pA4[qt]);
        Iq = __ldcs(&pI4[qt]);
    }
    __syncthreads();

    if (qt >= nquad) {
        cudaGridDependencySynchronize();
        cudaTriggerProgrammaticLaunchCompletion();
        return;
    }

    int4 ca = ((const int4*)sconn)[2 * tid + 0];   // {nA0,nB0,nA1,nB1}
    int4 cb = ((const int4*)sconn)[2 * tid + 1];   // {nA2,nB2,nA3,nB3}
    float4 q0 = ((const float4*)sdir)[3 * tid + 0];
    float4 q1 = ((const float4*)sdir)[3 * tid + 1];
    float4 q2 = ((const float4*)sdir)[3 * tid + 2];

    // ---- phase 2: wait for prep's completed writes, then gather/scatter ----
    cudaGridDependencySynchronize();

    float4 dA0 = __ldg(&g_pred4[ca.x]);
    float4 dB0 = __ldg(&g_pred4[ca.y]);
    float4 dA1 = __ldg(&g_pred4[ca.z]);
    float4 dB1 = __ldg(&g_pred4[ca.w]);
    float4 dA2 = __ldg(&g_pred4[cb.x]);
    float4 dB2 = __ldg(&g_pred4[cb.y]);
    float4 dA3 = __ldg(&g_pred4[cb.z]);
    float4 dB3 = __ldg(&g_pred4[cb.w]);

    float c0 = q0.x, s0 = q0.z;
    float c1 = q0.w, s1 = q1.y;
    float c2 = q1.z, s2 = q2.x;
    float c3 = q2.y, s3 = q2.w;

    float fAx, fAy, f2, f5;

    elem_force(c0, s0, dA0, dB0, Lq.x, Eq.x * Aq.x, Eq.x * Iq.x, fAx, fAy, f2, f5);
    red_v4(&g_Fint4[ca.x],  fAx,  fAy, -f2);
    red_v4(&g_Fint4[ca.y], -fAx, -fAy, -f5);

    elem_force(c1, s1, dA1, dB1, Lq.y, Eq.y * Aq.y, Eq.y * Iq.y, fAx, fAy, f2, f5);
    red_v4(&g_Fint4[ca.z],  fAx,  fAy, -f2);
    red_v4(&g_Fint4[ca.w], -fAx, -fAy, -f5);

    elem_force(c2, s2, dA2, dB2, Lq.z, Eq.z * Aq.z, Eq.z * Iq.z, fAx, fAy, f2, f5);
    red_v4(&g_Fint4[cb.x],  fAx,  fAy, -f2);
    red_v4(&g_Fint4[cb.y], -fAx, -fAy, -f5);

    elem_force(c3, s3, dA3, dB3, Lq.w, Eq.w * Aq.w, Eq.w * Iq.w, fAx, fAy, f2, f5);
    red_v4(&g_Fint4[cb.z],  fAx,  fAy, -f2);
    red_v4(&g_Fint4[cb.w], -fAx, -fAy, -f5);

    cudaTriggerProgrammaticLaunchCompletion();
}

// ---------------------------------------------------------------------------
// Kernel 3: node pass — lean R13 version: reads ONLY g_Fint4 (R + packed
// masks), coalesced 8-deep, fused divide + state reset. Trigger at end
// (releases next replay's prep).
// ---------------------------------------------------------------------------
__global__ void __launch_bounds__(256)
node_kernel(float* __restrict__ out, int N)
{
    cudaGridDependencySynchronize();

    int tid  = threadIdx.x;
    int base = blockIdx.x * 2048;

    float4 v[8];
    #pragma unroll
    for (int k = 0; k < 8; ++k) {
        int idx = base + k * 256 + tid;      // lane-contiguous: coalesced
        v[k] = (idx < N) ? g_Fint4[idx] : make_float4(0.f, 0.f, 0.f, 0.f);
    }

    float r2 = 0.f;
    #pragma unroll
    for (int k = 0; k < 8; ++k) {
        int iw = (int)v[k].w;
        float md = (float)(iw & 1);
        float mr = (float)(iw >> 1);
        float R0 = v[k].x * md;
        float R1 = v[k].y * md;
        float R2 = v[k].z * mr;
        r2 += R0 * R0 + R1 * R1 + R2 * R2;
    }

    for (int off = 16; off > 0; off >>= 1)
        r2 += __shfl_down_sync(0xffffffffu, r2, off);

    __shared__ float sr[8];
    int lane = tid & 31;
    int wid  = tid >> 5;
    if (lane == 0) sr[wid] = r2;
    __syncthreads();

    if (wid == 0) {
        float rr = (lane < 8) ? sr[lane] : 0.f;
        for (int off = 4; off > 0; off >>= 1)
            rr += __shfl_down_sync(0xffffffffu, rr, off);
        if (lane == 0) {
            atomicAdd(&g_acc[0], (double)rr);
            __threadfence();
            unsigned ticket = atomicAdd(&g_done, 1u);
            if (ticket == gridDim.x - 1) {
                double fn = g_acc[1];
                if (fn < 1e-30) fn = 1e-30;
                out[0] = (float)(g_acc[0] / fn);
                g_acc[0] = 0.0;
                g_acc[1] = 0.0;
                g_done = 0u;
            }
        }
    }

    cudaTriggerProgrammaticLaunchCompletion();
}

// ---------------------------------------------------------------------------
// Launch — all three via PDL (prep benefits across replay boundaries)
// ---------------------------------------------------------------------------
extern "C" void kernel_launch(void* const* d_in, const int* in_sizes, int n_in,
                              void* d_out, int out_size)
{
    const float* pred_raw = (const float*)d_in[0];   // [N,3]
    const float* u_c      = (const float*)d_in[1];   // [1]
    const float* theta_c  = (const float*)d_in[2];   // [1]
    const float* elem_len = (const float*)d_in[3];   // [E]
    const float* prop_E   = (const float*)d_in[4];   // [E]
    const float* prop_A   = (const float*)d_in[5];   // [E]
    const float* prop_I   = (const float*)d_in[6];   // [E]
    const float* dirs     = (const float*)d_in[7];   // [E,3]
    const float* F_ext    = (const float*)d_in[8];   // [N,3]
    const float* bc_disp  = (const float*)d_in[9];   // [N,1]
    const float* bc_rot   = (const float*)d_in[10];  // [N,1]
    const int*   conn     = (const int*)d_in[11];    // [E,2]

    int N = in_sizes[0] / 3;
    int E = in_sizes[3];

    float* out = (float*)d_out;

    cudaLaunchAttribute attr[1];
    attr[0].id = cudaLaunchAttributeProgrammaticStreamSerialization;
    attr[0].val.programmaticStreamSerializationAllowed = 1;

    // K1: prep with PDL (overlaps previous replay's node_kernel)
    {
        cudaLaunchConfig_t cfg = {};
        cfg.gridDim  = dim3((N + NPB - 1) / NPB);
        cfg.blockDim = dim3(PTB);
        cfg.dynamicSmemBytes = 0;
        cfg.stream = 0;
        cfg.attrs = attr;
        cfg.numAttrs = 1;
        cudaLaunchKernelEx(&cfg, prep_kernel,
                           (const float4*)pred_raw, (const float4*)F_ext,
                           bc_disp, bc_rot, u_c, theta_c, N);
    }

    // K2: elem with PDL
    {
        cudaLaunchConfig_t cfg = {};
        cfg.gridDim  = dim3((E + EPB - 1) / EPB);
        cfg.blockDim = dim3(ETB);
        cfg.dynamicSmemBytes = 0;
        cfg.stream = 0;
        cfg.attrs = attr;
        cfg.numAttrs = 1;
        cudaLaunchKernelEx(&cfg, elem_kernel,
                           (const float4*)elem_len, (const float4*)prop_E,
                           (const float4*)prop_A, (const float4*)prop_I,
                           (const float4*)dirs, (const int4*)conn, E);
    }

    // K3: node with PDL
    {
        cudaLaunchConfig_t cfg = {};
        cfg.gridDim  = dim3((N + 2047) / 2048);
        cfg.blockDim = dim3(256);
        cfg.dynamicSmemBytes = 0;
        cfg.stream = 0;
        cfg.attrs = attr;
        cfg.numAttrs = 1;
        cudaLaunchKernelEx(&cfg, node_kernel, out, N);
    }
}